// round 5
// baseline (speedup 1.0000x reference)
#include <cuda_runtime.h>
#include <cuda_fp16.h>
#include <cstdint>

#define NN 40000
#define EE 640000
#define BB 256

// ---------------- scratch (device globals; no allocation) ----------------
__device__ __half g_yl[NN * 128];      // lin_l output (gathered) fp16
__device__ __half g_yr[NN * 128];      // lin_r output fp16
__device__ float g_h1[NN * 128];
__device__ float g_h2[NN * 128];
__device__ float g_inv[NN];
__device__ int   g_dc[2 * NN];         // deg | cursor
__device__ int   g_start[NN + 1];
__device__ int   g_csr[EE];            // src ids sorted by dst
__device__ int   g_seg[BB + 1];
__device__ float g_Wc[512 * 256];      // [Wih[:,:128]+Whh | Wih[:,128:]]
__device__ float g_bl[512];            // bih + bhh
__device__ float g_s1[128], g_t1[128], g_s2[128], g_t2[128];

// ---------------- helpers ----------------
__device__ __forceinline__ float sigmoidf_(float x) { return 1.f / (1.f + expf(-x)); }

__device__ __forceinline__ float to_tf32(float x) {
    uint32_t u;
    asm("cvt.rna.tf32.f32 %0, %1;" : "=r"(u) : "f"(x));
    return __uint_as_float(u);
}

__device__ __forceinline__ void mma_tf32(float c[4], uint32_t a0, uint32_t a1,
                                         uint32_t a2, uint32_t a3,
                                         uint32_t b0, uint32_t b1) {
    asm volatile(
        "mma.sync.aligned.m16n8k8.row.col.f32.tf32.tf32.f32 "
        "{%0,%1,%2,%3}, {%4,%5,%6,%7}, {%8,%9}, {%0,%1,%2,%3};\n"
        : "+f"(c[0]), "+f"(c[1]), "+f"(c[2]), "+f"(c[3])
        : "r"(a0), "r"(a1), "r"(a2), "r"(a3), "r"(b0), "r"(b1));
}

__device__ __forceinline__ float dot8(float4 w0, float4 w1, float4 v0, float4 v1) {
    return w0.x * v0.x + w0.y * v0.y + w0.z * v0.z + w0.w * v0.w
         + w1.x * v1.x + w1.y * v1.y + w1.z * v1.z + w1.w * v1.w;
}

// ---------------- zero CSR counters (main stream, ahead of hist) ----------------
__global__ void k_zdc() {
    int i = blockIdx.x * blockDim.x + threadIdx.x;
    if (i < 2 * NN) g_dc[i] = 0;
}

// ---------------- pack Wc/bl, fold BN, segment bounds (side stream) ----------------
__global__ void k_pack(const float* __restrict__ Wih, const float* __restrict__ Whh,
                       const float* __restrict__ bih, const float* __restrict__ bhh,
                       const float* __restrict__ g1, const float* __restrict__ be1,
                       const float* __restrict__ rm1, const float* __restrict__ rv1,
                       const float* __restrict__ b1l,
                       const float* __restrict__ g2, const float* __restrict__ be2,
                       const float* __restrict__ rm2, const float* __restrict__ rv2,
                       const float* __restrict__ b2l,
                       const int* __restrict__ batch) {
    int i = blockIdx.x * blockDim.x + threadIdx.x;
    if (i < 512 * 256) {
        int r = i >> 8, k = i & 255;
        float w = Wih[r * 256 + k];
        if (k < 128) w += Whh[r * 128 + k];
        g_Wc[i] = w;
    }
    if (i < 512) g_bl[i] = bih[i] + bhh[i];
    if (i < 128) {
        float s = g1[i] * rsqrtf(rv1[i] + 1e-5f);
        g_s1[i] = s; g_t1[i] = be1[i] + (b1l[i] - rm1[i]) * s;
    } else if (i < 256) {
        int j = i - 128;
        float s = g2[j] * rsqrtf(rv2[j] + 1e-5f);
        g_s2[j] = s; g_t2[j] = be2[j] + (b2l[j] - rm2[j]) * s;
    }
    if (i < NN) {
        int b = batch[i];
        int prev = (i == 0) ? -1 : batch[i - 1];
        for (int q = prev + 1; q <= b; q++) g_seg[q] = i;
        if (i == NN - 1)
            for (int q = b + 1; q <= BB; q++) g_seg[q] = NN;
    }
}

// ---------------- CSR build ----------------
__global__ void k_hist(const int* __restrict__ ei) {
    int e = blockIdx.x * blockDim.x + threadIdx.x;
    if (e < EE) atomicAdd(&g_dc[ei[EE + e]], 1);
}

__global__ void k_scan() {  // single block, 1024 threads
    __shared__ int part[1024];
    int tid = threadIdx.x;
    const int chunk = (NN + 1023) / 1024;
    int b0 = tid * chunk, b1 = min(b0 + chunk, NN);
    int s = 0;
    for (int i = b0; i < b1; i++) s += g_dc[i];
    part[tid] = s;
    __syncthreads();
    for (int off = 1; off < 1024; off <<= 1) {
        int v = (tid >= off) ? part[tid - off] : 0;
        __syncthreads();
        part[tid] += v;
        __syncthreads();
    }
    int base = (tid == 0) ? 0 : part[tid - 1];
    for (int i = b0; i < b1; i++) {
        int d = g_dc[i];
        g_start[i] = base;
        g_inv[i] = 1.f / (float)max(d, 1);
        base += d;
    }
    if (tid == 1023) g_start[NN] = base;
}

__global__ void k_fill(const int* __restrict__ ei) {
    int e = blockIdx.x * blockDim.x + threadIdx.x;
    if (e >= EE) return;
    int s = ei[e], d = ei[EE + e];
    int pos = g_start[d] + atomicAdd(&g_dc[NN + d], 1);
    g_csr[pos] = s;
}

// ---------------- tf32 tensor-core GEMM: Yl/Yr = A @ Wl^T / Wr^T (fp16 out) ----------------
__global__ __launch_bounds__(256) void k_gemm_tf32(
    const float* __restrict__ A,
    const float* __restrict__ Wl, const float* __restrict__ Wr,
    __half* __restrict__ Yl, __half* __restrict__ Yr) {
    __shared__ float As[32][133];   // [k][m]
    __shared__ float Bs[32][133];   // [k][n]
    const float* W = blockIdx.y ? Wr : Wl;
    __half* Y = blockIdx.y ? Yr : Yl;
    int m0 = blockIdx.x * 128;
    int tid = threadIdx.x;
    int warp = tid >> 5, lane = tid & 31;
    int wm = warp >> 1, wn = warp & 1;
    int gid = lane >> 2, tig = lane & 3;

    float acc[2][8][4];
#pragma unroll
    for (int i = 0; i < 2; i++)
#pragma unroll
        for (int j = 0; j < 8; j++)
#pragma unroll
            for (int q = 0; q < 4; q++) acc[i][j][q] = 0.f;

    int lrow = tid >> 3;
    int lk4 = (tid & 7) * 4;

    for (int kc = 0; kc < 128; kc += 32) {
#pragma unroll
        for (int i = 0; i < 4; i++) {
            int r = m0 + lrow + 32 * i;
            int rc = min(r, NN - 1);
            float4 v = *(const float4*)(A + (size_t)rc * 128 + kc + lk4);
            As[lk4 + 0][lrow + 32 * i] = to_tf32(v.x);
            As[lk4 + 1][lrow + 32 * i] = to_tf32(v.y);
            As[lk4 + 2][lrow + 32 * i] = to_tf32(v.z);
            As[lk4 + 3][lrow + 32 * i] = to_tf32(v.w);
            float4 w = *(const float4*)(W + (size_t)(lrow + 32 * i) * 128 + kc + lk4);
            Bs[lk4 + 0][lrow + 32 * i] = to_tf32(w.x);
            Bs[lk4 + 1][lrow + 32 * i] = to_tf32(w.y);
            Bs[lk4 + 2][lrow + 32 * i] = to_tf32(w.z);
            Bs[lk4 + 3][lrow + 32 * i] = to_tf32(w.w);
        }
        __syncthreads();
#pragma unroll
        for (int ks = 0; ks < 32; ks += 8) {
            uint32_t a[2][4];
#pragma unroll
            for (int mt = 0; mt < 2; mt++) {
                int mb = wm * 32 + mt * 16;
                a[mt][0] = __float_as_uint(As[ks + tig][mb + gid]);
                a[mt][1] = __float_as_uint(As[ks + tig][mb + gid + 8]);
                a[mt][2] = __float_as_uint(As[ks + tig + 4][mb + gid]);
                a[mt][3] = __float_as_uint(As[ks + tig + 4][mb + gid + 8]);
            }
#pragma unroll
            for (int nt = 0; nt < 8; nt++) {
                int nb = wn * 64 + nt * 8;
                uint32_t b0 = __float_as_uint(Bs[ks + tig][nb + gid]);
                uint32_t b1 = __float_as_uint(Bs[ks + tig + 4][nb + gid]);
                mma_tf32(acc[0][nt], a[0][0], a[0][1], a[0][2], a[0][3], b0, b1);
                mma_tf32(acc[1][nt], a[1][0], a[1][1], a[1][2], a[1][3], b0, b1);
            }
        }
        __syncthreads();
    }

    int ncol0 = wn * 64;
#pragma unroll
    for (int mt = 0; mt < 2; mt++) {
        int row0 = m0 + wm * 32 + mt * 16 + gid;
        int row1 = row0 + 8;
#pragma unroll
        for (int nt = 0; nt < 8; nt++) {
            int c = ncol0 + nt * 8 + tig * 2;
            if (row0 < NN)
                *(__half2*)(Y + (size_t)row0 * 128 + c) =
                    __floats2half2_rn(acc[mt][nt][0], acc[mt][nt][1]);
            if (row1 < NN)
                *(__half2*)(Y + (size_t)row1 * 128 + c) =
                    __floats2half2_rn(acc[mt][nt][2], acc[mt][nt][3]);
        }
    }
}

// ---------------- CSR aggregation + epilogue (fp16 gather, fp32 accum) ----------------
__global__ void k_agg(const float* __restrict__ s, const float* __restrict__ t,
                      float* __restrict__ out) {
    int gt = blockIdx.x * blockDim.x + threadIdx.x;
    int w = gt >> 5;
    if (w >= NN) return;
    int lane = gt & 31;
    int e0 = g_start[w], e1 = g_start[w + 1];
    float4 acc0 = make_float4(0.f, 0.f, 0.f, 0.f);
    float4 acc1 = make_float4(0.f, 0.f, 0.f, 0.f);
    const uint2* Yl2 = (const uint2*)g_yl;
    int e = e0;
    for (; e + 2 <= e1; e += 2) {
        int sa = __ldg(g_csr + e);
        int sb = __ldg(g_csr + e + 1);
        uint2 ua = Yl2[(size_t)sa * 32 + lane];
        uint2 ub = Yl2[(size_t)sb * 32 + lane];
        float2 a0 = __half22float2(*(__half2*)&ua.x);
        float2 a1 = __half22float2(*(__half2*)&ua.y);
        float2 b0 = __half22float2(*(__half2*)&ub.x);
        float2 b1 = __half22float2(*(__half2*)&ub.y);
        acc0.x += a0.x; acc0.y += a0.y; acc0.z += a1.x; acc0.w += a1.y;
        acc1.x += b0.x; acc1.y += b0.y; acc1.z += b1.x; acc1.w += b1.y;
    }
    if (e < e1) {
        int sa = __ldg(g_csr + e);
        uint2 ua = Yl2[(size_t)sa * 32 + lane];
        float2 a0 = __half22float2(*(__half2*)&ua.x);
        float2 a1 = __half22float2(*(__half2*)&ua.y);
        acc0.x += a0.x; acc0.y += a0.y; acc0.z += a1.x; acc0.w += a1.y;
    }
    acc0.x += acc1.x; acc0.y += acc1.y; acc0.z += acc1.z; acc0.w += acc1.w;
    float iv = g_inv[w];
    uint2 ur = ((const uint2*)g_yr)[(size_t)w * 32 + lane];
    float2 r0 = __half22float2(*(__half2*)&ur.x);
    float2 r1 = __half22float2(*(__half2*)&ur.y);
    float4 sv = ((const float4*)s)[lane];
    float4 tv = ((const float4*)t)[lane];
    float4 o;
    o.x = fmaxf(fmaf(fmaf(acc0.x, iv, r0.x), sv.x, tv.x), 0.f);
    o.y = fmaxf(fmaf(fmaf(acc0.y, iv, r0.y), sv.y, tv.y), 0.f);
    o.z = fmaxf(fmaf(fmaf(acc0.z, iv, r1.x), sv.z, tv.z), 0.f);
    o.w = fmaxf(fmaf(fmaf(acc0.w, iv, r1.y), sv.w, tv.w), 0.f);
    ((float4*)out)[(size_t)w * 32 + lane] = o;
}

// ---------------- fully fused set2set (3 steps) + final projection ----------------
// 64 blocks x 256 threads; each block owns 4 graphs. Gate/projection weight rows
// are loaded once per block and serve all 4 graphs. Attention: 2 warps per graph.
__global__ __launch_bounds__(256) void k_s2s(const float* __restrict__ Wp,
                                             const float* __restrict__ bp,
                                             float* __restrict__ out) {
    int blk = blockIdx.x;
    int tid = threadIdx.x;
    int warp = tid >> 5, lane = tid & 31;
    int gr = warp >> 1;              // graph slot 0..3
    int wl = warp & 1;               // warp-local index within graph
    int g = blk * 4 + gr;

    __shared__ float sh_v[4][256];       // q_star = [q | r]
    __shared__ float sh_q[4][128];
    __shared__ float sh_c[4][128];
    __shared__ float sh_gates[4][512];
    __shared__ float sh_r[4][2][128];
    __shared__ float sh_s[4][4];         // [graph][0..1 = max, 2..3 = sum]

    for (int i = tid; i < 512; i += 256) sh_c[i >> 7][i & 127] = 0.f;
    __syncthreads();

    int s0 = g_seg[g], s1 = g_seg[g + 1];
    const float4* H4 = (const float4*)g_h2;

    for (int step = 0; step < 3; step++) {
        // ---- gates ----
        if (step == 0) {
            for (int i = tid; i < 2048; i += 256) {
                int gg = i >> 9, r = i & 511;
                sh_gates[gg][r] = g_bl[r];
            }
        } else {
            float4 v0[4], v1[4];
#pragma unroll
            for (int q = 0; q < 4; q++) {
                const float4* V = (const float4*)sh_v[q];
                v0[q] = V[lane]; v1[q] = V[32 + lane];
            }
#pragma unroll 2
            for (int j = 0; j < 64; j++) {
                int r = warp * 64 + j;
                const float4* Wr4 = (const float4*)(g_Wc + (size_t)r * 256);
                float4 w0 = Wr4[lane], w1 = Wr4[32 + lane];
                float p0 = dot8(w0, w1, v0[0], v1[0]);
                float p1 = dot8(w0, w1, v0[1], v1[1]);
                float p2 = dot8(w0, w1, v0[2], v1[2]);
                float p3 = dot8(w0, w1, v0[3], v1[3]);
#pragma unroll
                for (int o = 16; o > 0; o >>= 1) {
                    p0 += __shfl_xor_sync(0xffffffffu, p0, o);
                    p1 += __shfl_xor_sync(0xffffffffu, p1, o);
                    p2 += __shfl_xor_sync(0xffffffffu, p2, o);
                    p3 += __shfl_xor_sync(0xffffffffu, p3, o);
                }
                if (lane == 0) {
                    float bb = g_bl[r];
                    sh_gates[0][r] = p0 + bb;
                    sh_gates[1][r] = p1 + bb;
                    sh_gates[2][r] = p2 + bb;
                    sh_gates[3][r] = p3 + bb;
                }
            }
        }
        __syncthreads();

        // ---- LSTM cell (4 graphs x 128 dims over 256 threads) ----
        for (int i = tid; i < 512; i += 256) {
            int gg = i >> 7, d = i & 127;
            float ig = sh_gates[gg][d], fg = sh_gates[gg][128 + d];
            float gv = sh_gates[gg][256 + d], og = sh_gates[gg][384 + d];
            float c0 = sh_c[gg][d];
            float cn = sigmoidf_(fg) * c0 + sigmoidf_(ig) * tanhf(gv);
            float hn = sigmoidf_(og) * tanhf(cn);
            sh_c[gg][d] = cn;
            sh_q[gg][d] = hn;
        }
        __syncthreads();

        // ---- attention pass 1: segment max ----
        float4 qv = ((const float4*)sh_q[gr])[lane];
        float wmax = -3.402823466e38f;
        for (int n = s0 + wl; n < s1; n += 2) {
            float4 hv = H4[(size_t)n * 32 + lane];
            float p = hv.x * qv.x + hv.y * qv.y + hv.z * qv.z + hv.w * qv.w;
#pragma unroll
            for (int o = 16; o > 0; o >>= 1) p += __shfl_xor_sync(0xffffffffu, p, o);
            wmax = fmaxf(wmax, p);
        }
        if (lane == 0) sh_s[gr][wl] = wmax;
        __syncthreads();
        float emax = fmaxf(sh_s[gr][0], sh_s[gr][1]);

        // ---- attention pass 2: exp-sum + weighted feature sum ----
        float asum = 0.f;
        float4 racc = make_float4(0.f, 0.f, 0.f, 0.f);
        for (int n = s0 + wl; n < s1; n += 2) {
            float4 hv = H4[(size_t)n * 32 + lane];
            float p = hv.x * qv.x + hv.y * qv.y + hv.z * qv.z + hv.w * qv.w;
#pragma unroll
            for (int o = 16; o > 0; o >>= 1) p += __shfl_xor_sync(0xffffffffu, p, o);
            float a = expf(p - emax);
            asum += a;
            racc.x += a * hv.x; racc.y += a * hv.y; racc.z += a * hv.z; racc.w += a * hv.w;
        }
        ((float4*)sh_r[gr][wl])[lane] = racc;
        if (lane == 0) sh_s[gr][2 + wl] = asum;
        __syncthreads();

        // ---- combine: q_star = [q | r] ----
        for (int i = tid; i < 512; i += 256) {
            int gg = i >> 7, d = i & 127;
            float den = sh_s[gg][2] + sh_s[gg][3];
            float rsum = sh_r[gg][0][d] + sh_r[gg][1][d];
            float r = (den > 0.f) ? rsum / den : 0.f;
            sh_v[gg][d] = sh_q[gg][d];
            sh_v[gg][128 + d] = r;
        }
        __syncthreads();
    }

    // ---- final projection: each Wp row serves all 4 graphs ----
    {
        float4 v0[4], v1[4];
#pragma unroll
        for (int q = 0; q < 4; q++) {
            const float4* V = (const float4*)sh_v[q];
            v0[q] = V[lane]; v1[q] = V[32 + lane];
        }
#pragma unroll 2
        for (int j = 0; j < 16; j++) {
            int row = warp * 16 + j;
            const float4* Wr4 = (const float4*)(Wp + (size_t)row * 256);
            float4 w0 = Wr4[lane], w1 = Wr4[32 + lane];
            float p0 = dot8(w0, w1, v0[0], v1[0]);
            float p1 = dot8(w0, w1, v0[1], v1[1]);
            float p2 = dot8(w0, w1, v0[2], v1[2]);
            float p3 = dot8(w0, w1, v0[3], v1[3]);
#pragma unroll
            for (int o = 16; o > 0; o >>= 1) {
                p0 += __shfl_xor_sync(0xffffffffu, p0, o);
                p1 += __shfl_xor_sync(0xffffffffu, p1, o);
                p2 += __shfl_xor_sync(0xffffffffu, p2, o);
                p3 += __shfl_xor_sync(0xffffffffu, p3, o);
            }
            if (lane == 0) {
                float bb = bp[row];
                out[(blk * 4 + 0) * 128 + row] = p0 + bb;
                out[(blk * 4 + 1) * 128 + row] = p1 + bb;
                out[(blk * 4 + 2) * 128 + row] = p2 + bb;
                out[(blk * 4 + 3) * 128 + row] = p3 + bb;
            }
        }
    }
}

// ---------------- host ----------------
extern "C" void kernel_launch(void* const* d_in, const int* in_sizes, int n_in,
                              void* d_out, int out_size) {
    const float* x    = (const float*)d_in[0];
    const int*   ei   = (const int*)d_in[1];
    const int*   batch= (const int*)d_in[2];
    const float* W1l  = (const float*)d_in[3];
    const float* b1l  = (const float*)d_in[4];
    const float* W1r  = (const float*)d_in[5];
    const float* g1   = (const float*)d_in[6];
    const float* be1  = (const float*)d_in[7];
    const float* rm1  = (const float*)d_in[8];
    const float* rv1  = (const float*)d_in[9];
    const float* W2l  = (const float*)d_in[10];
    const float* b2l  = (const float*)d_in[11];
    const float* W2r  = (const float*)d_in[12];
    const float* g2   = (const float*)d_in[13];
    const float* be2  = (const float*)d_in[14];
    const float* rm2  = (const float*)d_in[15];
    const float* rv2  = (const float*)d_in[16];
    const float* Wih  = (const float*)d_in[17];
    const float* Whh  = (const float*)d_in[18];
    const float* bih  = (const float*)d_in[19];
    const float* bhh  = (const float*)d_in[20];
    const float* Wp   = (const float*)d_in[21];
    const float* bp   = (const float*)d_in[22];

    __half *p_yl, *p_yr;
    float *p_h1, *p_h2, *p_s1, *p_t1, *p_s2, *p_t2;
    cudaGetSymbolAddress((void**)&p_yl, g_yl);
    cudaGetSymbolAddress((void**)&p_yr, g_yr);
    cudaGetSymbolAddress((void**)&p_h1, g_h1);
    cudaGetSymbolAddress((void**)&p_h2, g_h2);
    cudaGetSymbolAddress((void**)&p_s1, g_s1);
    cudaGetSymbolAddress((void**)&p_t1, g_t1);
    cudaGetSymbolAddress((void**)&p_s2, g_s2);
    cudaGetSymbolAddress((void**)&p_t2, g_t2);

    // side stream + fork/join events, created once on the (uncaptured)
    // correctness call and reused inside graph capture thereafter.
    static cudaStream_t s_side = nullptr;
    static cudaEvent_t ev_fork = nullptr, ev_join = nullptr;
    if (s_side == nullptr) {
        cudaStreamCreateWithFlags(&s_side, cudaStreamNonBlocking);
        cudaEventCreateWithFlags(&ev_fork, cudaEventDisableTiming);
        cudaEventCreateWithFlags(&ev_join, cudaEventDisableTiming);
    }

    dim3 gL((NN + 127) / 128, 2);

    // fork: side stream does weight pack + layer-1 GEMM (independent of CSR)
    cudaEventRecord(ev_fork, 0);
    cudaStreamWaitEvent(s_side, ev_fork, 0);
    k_pack<<<512, 256, 0, s_side>>>(Wih, Whh, bih, bhh, g1, be1, rm1, rv1, b1l,
                                    g2, be2, rm2, rv2, b2l, batch);
    k_gemm_tf32<<<gL, 256, 0, s_side>>>(x, W1l, W1r, p_yl, p_yr);
    cudaEventRecord(ev_join, s_side);

    // main stream: CSR build (zero -> hist -> scan -> fill)
    k_zdc<<<(2 * NN + 255) / 256, 256>>>();
    k_hist<<<(EE + 255) / 256, 256>>>(ei);
    k_scan<<<1, 1024>>>();
    k_fill<<<(EE + 255) / 256, 256>>>(ei);

    // join: everything below needs both branches
    cudaStreamWaitEvent(0, ev_join, 0);

    // layer 1 aggregation, layer 2, set2set + projection
    k_agg<<<(NN * 32 + 255) / 256, 256>>>(p_s1, p_t1, p_h1);
    k_gemm_tf32<<<gL, 256>>>(p_h1, W2l, W2r, p_yl, p_yr);
    k_agg<<<(NN * 32 + 255) / 256, 256>>>(p_s2, p_t2, p_h2);
    k_s2s<<<BB / 4, 256>>>(Wp, bp, (float*)d_out);
}

// round 6
// speedup vs baseline: 1.5957x; 1.5957x over previous
#include <cuda_runtime.h>
#include <cuda_fp16.h>
#include <cstdint>

#define NN 40000
#define EE 640000
#define BB 256

// ---------------- scratch (device globals; no allocation, zero-initialized) ----------------
__device__ __half g_yl[NN * 128];      // lin_l output (gathered) fp16
__device__ __half g_yr[NN * 128];      // lin_r output fp16
__device__ float g_h1[NN * 128];       // layer-1 output (GEMM input) fp32
__device__ __half g_h2h[NN * 128];     // layer-2 output (s2s attention input) fp16
__device__ float g_inv[NN];
__device__ int   g_dc[2 * NN];         // deg | cursor (self-cleaning: k_scan re-zeroes)
__device__ int   g_start[NN + 1];
__device__ int   g_csr[EE];            // src ids sorted by dst
__device__ int   g_seg[BB + 1];
__device__ float g_Wc[512 * 256];      // [Wih[:,:128]+Whh | Wih[:,128:]]
__device__ float g_bl[512];            // bih + bhh
__device__ float g_s1[128], g_t1[128], g_s2[128], g_t2[128];

// ---------------- helpers ----------------
__device__ __forceinline__ float sigmoidf_(float x) { return 1.f / (1.f + expf(-x)); }

__device__ __forceinline__ float to_tf32(float x) {
    uint32_t u;
    asm("cvt.rna.tf32.f32 %0, %1;" : "=r"(u) : "f"(x));
    return __uint_as_float(u);
}

__device__ __forceinline__ void mma_tf32(float c[4], uint32_t a0, uint32_t a1,
                                         uint32_t a2, uint32_t a3,
                                         uint32_t b0, uint32_t b1) {
    asm volatile(
        "mma.sync.aligned.m16n8k8.row.col.f32.tf32.tf32.f32 "
        "{%0,%1,%2,%3}, {%4,%5,%6,%7}, {%8,%9}, {%0,%1,%2,%3};\n"
        : "+f"(c[0]), "+f"(c[1]), "+f"(c[2]), "+f"(c[3])
        : "r"(a0), "r"(a1), "r"(a2), "r"(a3), "r"(b0), "r"(b1));
}

__device__ __forceinline__ float dot8(float4 w0, float4 w1, float4 v0, float4 v1) {
    return w0.x * v0.x + w0.y * v0.y + w0.z * v0.z + w0.w * v0.w
         + w1.x * v1.x + w1.y * v1.y + w1.z * v1.z + w1.w * v1.w;
}

// ---------------- pack Wc/bl, fold BN, segment bounds ----------------
__global__ void k_prep(const float* __restrict__ Wih, const float* __restrict__ Whh,
                       const float* __restrict__ bih, const float* __restrict__ bhh,
                       const float* __restrict__ g1, const float* __restrict__ be1,
                       const float* __restrict__ rm1, const float* __restrict__ rv1,
                       const float* __restrict__ b1l,
                       const float* __restrict__ g2, const float* __restrict__ be2,
                       const float* __restrict__ rm2, const float* __restrict__ rv2,
                       const float* __restrict__ b2l,
                       const int* __restrict__ batch) {
    int i = blockIdx.x * blockDim.x + threadIdx.x;
    if (i < 512 * 256) {
        int r = i >> 8, k = i & 255;
        float w = Wih[r * 256 + k];
        if (k < 128) w += Whh[r * 128 + k];
        g_Wc[i] = w;
    }
    if (i < 512) g_bl[i] = bih[i] + bhh[i];
    if (i < 128) {
        float s = g1[i] * rsqrtf(rv1[i] + 1e-5f);
        g_s1[i] = s; g_t1[i] = be1[i] + (b1l[i] - rm1[i]) * s;
    } else if (i < 256) {
        int j = i - 128;
        float s = g2[j] * rsqrtf(rv2[j] + 1e-5f);
        g_s2[j] = s; g_t2[j] = be2[j] + (b2l[j] - rm2[j]) * s;
    }
    if (i < NN) {
        int b = batch[i];
        int prev = (i == 0) ? -1 : batch[i - 1];
        for (int q = prev + 1; q <= b; q++) g_seg[q] = i;
        if (i == NN - 1)
            for (int q = b + 1; q <= BB; q++) g_seg[q] = NN;
    }
}

// ---------------- CSR build (self-cleaning counters) ----------------
// Invariant at every kernel_launch entry: g_dc is all-zero.
//  - first call: device globals are zero-initialized
//  - later calls: k_scan below re-zeroed both halves last call
__global__ void k_hist(const int* __restrict__ ei) {
    int e = blockIdx.x * blockDim.x + threadIdx.x;
    if (e < EE) atomicAdd(&g_dc[ei[EE + e]], 1);
}

__global__ void k_scan() {  // single block, 1024 threads
    __shared__ int part[1024];
    int tid = threadIdx.x;
    const int chunk = (NN + 1023) / 1024;
    int b0 = tid * chunk, b1 = min(b0 + chunk, NN);
    int s = 0;
    for (int i = b0; i < b1; i++) s += g_dc[i];
    part[tid] = s;
    __syncthreads();
    for (int off = 1; off < 1024; off <<= 1) {
        int v = (tid >= off) ? part[tid - off] : 0;
        __syncthreads();
        part[tid] += v;
        __syncthreads();
    }
    int base = (tid == 0) ? 0 : part[tid - 1];
    for (int i = b0; i < b1; i++) {
        int d = g_dc[i];
        g_start[i] = base;
        g_inv[i] = 1.f / (float)max(d, 1);
        base += d;
        g_dc[i] = 0;          // re-zero degree half for next call
        g_dc[NN + i] = 0;     // zero cursor half for k_fill below
    }
    if (tid == 1023) g_start[NN] = base;
}

__global__ void k_fill(const int* __restrict__ ei) {
    int e = blockIdx.x * blockDim.x + threadIdx.x;
    if (e >= EE) return;
    int s = ei[e], d = ei[EE + e];
    int pos = g_start[d] + atomicAdd(&g_dc[NN + d], 1);
    g_csr[pos] = s;
}

// ---------------- tf32 tensor-core GEMM: Yl/Yr = A @ Wl^T / Wr^T (fp16 out) ----------------
__global__ __launch_bounds__(256) void k_gemm_tf32(
    const float* __restrict__ A,
    const float* __restrict__ Wl, const float* __restrict__ Wr,
    __half* __restrict__ Yl, __half* __restrict__ Yr) {
    __shared__ float As[32][133];   // [k][m]
    __shared__ float Bs[32][133];   // [k][n]
    const float* W = blockIdx.y ? Wr : Wl;
    __half* Y = blockIdx.y ? Yr : Yl;
    int m0 = blockIdx.x * 128;
    int tid = threadIdx.x;
    int warp = tid >> 5, lane = tid & 31;
    int wm = warp >> 1, wn = warp & 1;
    int gid = lane >> 2, tig = lane & 3;

    float acc[2][8][4];
#pragma unroll
    for (int i = 0; i < 2; i++)
#pragma unroll
        for (int j = 0; j < 8; j++)
#pragma unroll
            for (int q = 0; q < 4; q++) acc[i][j][q] = 0.f;

    int lrow = tid >> 3;
    int lk4 = (tid & 7) * 4;

    for (int kc = 0; kc < 128; kc += 32) {
#pragma unroll
        for (int i = 0; i < 4; i++) {
            int r = m0 + lrow + 32 * i;
            int rc = min(r, NN - 1);
            float4 v = *(const float4*)(A + (size_t)rc * 128 + kc + lk4);
            As[lk4 + 0][lrow + 32 * i] = to_tf32(v.x);
            As[lk4 + 1][lrow + 32 * i] = to_tf32(v.y);
            As[lk4 + 2][lrow + 32 * i] = to_tf32(v.z);
            As[lk4 + 3][lrow + 32 * i] = to_tf32(v.w);
            float4 w = *(const float4*)(W + (size_t)(lrow + 32 * i) * 128 + kc + lk4);
            Bs[lk4 + 0][lrow + 32 * i] = to_tf32(w.x);
            Bs[lk4 + 1][lrow + 32 * i] = to_tf32(w.y);
            Bs[lk4 + 2][lrow + 32 * i] = to_tf32(w.z);
            Bs[lk4 + 3][lrow + 32 * i] = to_tf32(w.w);
        }
        __syncthreads();
#pragma unroll
        for (int ks = 0; ks < 32; ks += 8) {
            uint32_t a[2][4];
#pragma unroll
            for (int mt = 0; mt < 2; mt++) {
                int mb = wm * 32 + mt * 16;
                a[mt][0] = __float_as_uint(As[ks + tig][mb + gid]);
                a[mt][1] = __float_as_uint(As[ks + tig][mb + gid + 8]);
                a[mt][2] = __float_as_uint(As[ks + tig + 4][mb + gid]);
                a[mt][3] = __float_as_uint(As[ks + tig + 4][mb + gid + 8]);
            }
#pragma unroll
            for (int nt = 0; nt < 8; nt++) {
                int nb = wn * 64 + nt * 8;
                uint32_t b0 = __float_as_uint(Bs[ks + tig][nb + gid]);
                uint32_t b1 = __float_as_uint(Bs[ks + tig + 4][nb + gid]);
                mma_tf32(acc[0][nt], a[0][0], a[0][1], a[0][2], a[0][3], b0, b1);
                mma_tf32(acc[1][nt], a[1][0], a[1][1], a[1][2], a[1][3], b0, b1);
            }
        }
        __syncthreads();
    }

    int ncol0 = wn * 64;
#pragma unroll
    for (int mt = 0; mt < 2; mt++) {
        int row0 = m0 + wm * 32 + mt * 16 + gid;
        int row1 = row0 + 8;
#pragma unroll
        for (int nt = 0; nt < 8; nt++) {
            int c = ncol0 + nt * 8 + tig * 2;
            if (row0 < NN)
                *(__half2*)(Y + (size_t)row0 * 128 + c) =
                    __floats2half2_rn(acc[mt][nt][0], acc[mt][nt][1]);
            if (row1 < NN)
                *(__half2*)(Y + (size_t)row1 * 128 + c) =
                    __floats2half2_rn(acc[mt][nt][2], acc[mt][nt][3]);
        }
    }
}

// ---------------- CSR aggregation + epilogue (fp16 gather, fp32 accum) ----------------
// fp16out=0 -> write fp32 to out32 (h1); fp16out=1 -> write fp16 to out16 (h2)
__global__ void k_agg(const float* __restrict__ s, const float* __restrict__ t,
                      float* __restrict__ out32, __half* __restrict__ out16,
                      int fp16out) {
    int gt = blockIdx.x * blockDim.x + threadIdx.x;
    int w = gt >> 5;
    if (w >= NN) return;
    int lane = gt & 31;
    int e0 = g_start[w], e1 = g_start[w + 1];
    float4 acc0 = make_float4(0.f, 0.f, 0.f, 0.f);
    float4 acc1 = make_float4(0.f, 0.f, 0.f, 0.f);
    const uint2* Yl2 = (const uint2*)g_yl;
    int e = e0;
    for (; e + 2 <= e1; e += 2) {
        int sa = __ldg(g_csr + e);
        int sb = __ldg(g_csr + e + 1);
        uint2 ua = Yl2[(size_t)sa * 32 + lane];
        uint2 ub = Yl2[(size_t)sb * 32 + lane];
        float2 a0 = __half22float2(*(__half2*)&ua.x);
        float2 a1 = __half22float2(*(__half2*)&ua.y);
        float2 b0 = __half22float2(*(__half2*)&ub.x);
        float2 b1 = __half22float2(*(__half2*)&ub.y);
        acc0.x += a0.x; acc0.y += a0.y; acc0.z += a1.x; acc0.w += a1.y;
        acc1.x += b0.x; acc1.y += b0.y; acc1.z += b1.x; acc1.w += b1.y;
    }
    if (e < e1) {
        int sa = __ldg(g_csr + e);
        uint2 ua = Yl2[(size_t)sa * 32 + lane];
        float2 a0 = __half22float2(*(__half2*)&ua.x);
        float2 a1 = __half22float2(*(__half2*)&ua.y);
        acc0.x += a0.x; acc0.y += a0.y; acc0.z += a1.x; acc0.w += a1.y;
    }
    acc0.x += acc1.x; acc0.y += acc1.y; acc0.z += acc1.z; acc0.w += acc1.w;
    float iv = g_inv[w];
    uint2 ur = ((const uint2*)g_yr)[(size_t)w * 32 + lane];
    float2 r0 = __half22float2(*(__half2*)&ur.x);
    float2 r1 = __half22float2(*(__half2*)&ur.y);
    float4 sv = ((const float4*)s)[lane];
    float4 tv = ((const float4*)t)[lane];
    float4 o;
    o.x = fmaxf(fmaf(fmaf(acc0.x, iv, r0.x), sv.x, tv.x), 0.f);
    o.y = fmaxf(fmaf(fmaf(acc0.y, iv, r0.y), sv.y, tv.y), 0.f);
    o.z = fmaxf(fmaf(fmaf(acc0.z, iv, r1.x), sv.z, tv.z), 0.f);
    o.w = fmaxf(fmaf(fmaf(acc0.w, iv, r1.y), sv.w, tv.w), 0.f);
    if (fp16out) {
        uint2 pk;
        *(__half2*)&pk.x = __floats2half2_rn(o.x, o.y);
        *(__half2*)&pk.y = __floats2half2_rn(o.z, o.w);
        ((uint2*)out16)[(size_t)w * 32 + lane] = pk;
    } else {
        ((float4*)out32)[(size_t)w * 32 + lane] = o;
    }
}

// ---------------- fully fused set2set (3 steps) + final projection ----------------
// 64 blocks x 256 threads; each block owns 4 graphs. Gate/projection weight rows
// are loaded once per block and serve all 4 graphs. Attention: 2 warps per graph.
// h2 is fp16 (g_h2h).
__global__ __launch_bounds__(256) void k_s2s(const float* __restrict__ Wp,
                                             const float* __restrict__ bp,
                                             float* __restrict__ out) {
    int blk = blockIdx.x;
    int tid = threadIdx.x;
    int warp = tid >> 5, lane = tid & 31;
    int gr = warp >> 1;              // graph slot 0..3
    int wl = warp & 1;               // warp-local index within graph
    int g = blk * 4 + gr;

    __shared__ float sh_v[4][256];       // q_star = [q | r]
    __shared__ float sh_q[4][128];
    __shared__ float sh_c[4][128];
    __shared__ float sh_gates[4][512];
    __shared__ float sh_r[4][2][128];
    __shared__ float sh_s[4][4];         // [graph][0..1 = max, 2..3 = sum]

    for (int i = tid; i < 512; i += 256) sh_c[i >> 7][i & 127] = 0.f;
    __syncthreads();

    int s0 = g_seg[g], s1 = g_seg[g + 1];
    const uint2* H2 = (const uint2*)g_h2h;   // 4 halves per uint2; row = 32 uint2

    for (int step = 0; step < 3; step++) {
        // ---- gates ----
        if (step == 0) {
            for (int i = tid; i < 2048; i += 256) {
                int gg = i >> 9, r = i & 511;
                sh_gates[gg][r] = g_bl[r];
            }
        } else {
            float4 v0[4], v1[4];
#pragma unroll
            for (int q = 0; q < 4; q++) {
                const float4* V = (const float4*)sh_v[q];
                v0[q] = V[lane]; v1[q] = V[32 + lane];
            }
#pragma unroll 2
            for (int j = 0; j < 64; j++) {
                int r = warp * 64 + j;
                const float4* Wr4 = (const float4*)(g_Wc + (size_t)r * 256);
                float4 w0 = Wr4[lane], w1 = Wr4[32 + lane];
                float p0 = dot8(w0, w1, v0[0], v1[0]);
                float p1 = dot8(w0, w1, v0[1], v1[1]);
                float p2 = dot8(w0, w1, v0[2], v1[2]);
                float p3 = dot8(w0, w1, v0[3], v1[3]);
#pragma unroll
                for (int o = 16; o > 0; o >>= 1) {
                    p0 += __shfl_xor_sync(0xffffffffu, p0, o);
                    p1 += __shfl_xor_sync(0xffffffffu, p1, o);
                    p2 += __shfl_xor_sync(0xffffffffu, p2, o);
                    p3 += __shfl_xor_sync(0xffffffffu, p3, o);
                }
                if (lane == 0) {
                    float bb = g_bl[r];
                    sh_gates[0][r] = p0 + bb;
                    sh_gates[1][r] = p1 + bb;
                    sh_gates[2][r] = p2 + bb;
                    sh_gates[3][r] = p3 + bb;
                }
            }
        }
        __syncthreads();

        // ---- LSTM cell (4 graphs x 128 dims over 256 threads) ----
        for (int i = tid; i < 512; i += 256) {
            int gg = i >> 7, d = i & 127;
            float ig = sh_gates[gg][d], fg = sh_gates[gg][128 + d];
            float gv = sh_gates[gg][256 + d], og = sh_gates[gg][384 + d];
            float c0 = sh_c[gg][d];
            float cn = sigmoidf_(fg) * c0 + sigmoidf_(ig) * tanhf(gv);
            float hn = sigmoidf_(og) * tanhf(cn);
            sh_c[gg][d] = cn;
            sh_q[gg][d] = hn;
        }
        __syncthreads();

        // ---- attention pass 1: segment max ----
        float4 qv = ((const float4*)sh_q[gr])[lane];
        float wmax = -3.402823466e38f;
        for (int n = s0 + wl; n < s1; n += 2) {
            uint2 u = H2[(size_t)n * 32 + lane];
            float2 h0 = __half22float2(*(__half2*)&u.x);
            float2 h1 = __half22float2(*(__half2*)&u.y);
            float p = h0.x * qv.x + h0.y * qv.y + h1.x * qv.z + h1.y * qv.w;
#pragma unroll
            for (int o = 16; o > 0; o >>= 1) p += __shfl_xor_sync(0xffffffffu, p, o);
            wmax = fmaxf(wmax, p);
        }
        if (lane == 0) sh_s[gr][wl] = wmax;
        __syncthreads();
        float emax = fmaxf(sh_s[gr][0], sh_s[gr][1]);

        // ---- attention pass 2: exp-sum + weighted feature sum ----
        float asum = 0.f;
        float4 racc = make_float4(0.f, 0.f, 0.f, 0.f);
        for (int n = s0 + wl; n < s1; n += 2) {
            uint2 u = H2[(size_t)n * 32 + lane];
            float2 h0 = __half22float2(*(__half2*)&u.x);
            float2 h1 = __half22float2(*(__half2*)&u.y);
            float p = h0.x * qv.x + h0.y * qv.y + h1.x * qv.z + h1.y * qv.w;
#pragma unroll
            for (int o = 16; o > 0; o >>= 1) p += __shfl_xor_sync(0xffffffffu, p, o);
            float a = expf(p - emax);
            asum += a;
            racc.x += a * h0.x; racc.y += a * h0.y; racc.z += a * h1.x; racc.w += a * h1.y;
        }
        ((float4*)sh_r[gr][wl])[lane] = racc;
        if (lane == 0) sh_s[gr][2 + wl] = asum;
        __syncthreads();

        // ---- combine: q_star = [q | r] ----
        for (int i = tid; i < 512; i += 256) {
            int gg = i >> 7, d = i & 127;
            float den = sh_s[gg][2] + sh_s[gg][3];
            float rsum = sh_r[gg][0][d] + sh_r[gg][1][d];
            float r = (den > 0.f) ? rsum / den : 0.f;
            sh_v[gg][d] = sh_q[gg][d];
            sh_v[gg][128 + d] = r;
        }
        __syncthreads();
    }

    // ---- final projection: each Wp row serves all 4 graphs ----
    {
        float4 v0[4], v1[4];
#pragma unroll
        for (int q = 0; q < 4; q++) {
            const float4* V = (const float4*)sh_v[q];
            v0[q] = V[lane]; v1[q] = V[32 + lane];
        }
#pragma unroll 2
        for (int j = 0; j < 16; j++) {
            int row = warp * 16 + j;
            const float4* Wr4 = (const float4*)(Wp + (size_t)row * 256);
            float4 w0 = Wr4[lane], w1 = Wr4[32 + lane];
            float p0 = dot8(w0, w1, v0[0], v1[0]);
            float p1 = dot8(w0, w1, v0[1], v1[1]);
            float p2 = dot8(w0, w1, v0[2], v1[2]);
            float p3 = dot8(w0, w1, v0[3], v1[3]);
#pragma unroll
            for (int o = 16; o > 0; o >>= 1) {
                p0 += __shfl_xor_sync(0xffffffffu, p0, o);
                p1 += __shfl_xor_sync(0xffffffffu, p1, o);
                p2 += __shfl_xor_sync(0xffffffffu, p2, o);
                p3 += __shfl_xor_sync(0xffffffffu, p3, o);
            }
            if (lane == 0) {
                float bb = bp[row];
                out[(blk * 4 + 0) * 128 + row] = p0 + bb;
                out[(blk * 4 + 1) * 128 + row] = p1 + bb;
                out[(blk * 4 + 2) * 128 + row] = p2 + bb;
                out[(blk * 4 + 3) * 128 + row] = p3 + bb;
            }
        }
    }
}

// ---------------- host ----------------
extern "C" void kernel_launch(void* const* d_in, const int* in_sizes, int n_in,
                              void* d_out, int out_size) {
    const float* x    = (const float*)d_in[0];
    const int*   ei   = (const int*)d_in[1];
    const int*   batch= (const int*)d_in[2];
    const float* W1l  = (const float*)d_in[3];
    const float* b1l  = (const float*)d_in[4];
    const float* W1r  = (const float*)d_in[5];
    const float* g1   = (const float*)d_in[6];
    const float* be1  = (const float*)d_in[7];
    const float* rm1  = (const float*)d_in[8];
    const float* rv1  = (const float*)d_in[9];
    const float* W2l  = (const float*)d_in[10];
    const float* b2l  = (const float*)d_in[11];
    const float* W2r  = (const float*)d_in[12];
    const float* g2   = (const float*)d_in[13];
    const float* be2  = (const float*)d_in[14];
    const float* rm2  = (const float*)d_in[15];
    const float* rv2  = (const float*)d_in[16];
    const float* Wih  = (const float*)d_in[17];
    const float* Whh  = (const float*)d_in[18];
    const float* bih  = (const float*)d_in[19];
    const float* bhh  = (const float*)d_in[20];
    const float* Wp   = (const float*)d_in[21];
    const float* bp   = (const float*)d_in[22];

    __half *p_yl, *p_yr, *p_h2;
    float *p_h1, *p_s1, *p_t1, *p_s2, *p_t2;
    cudaGetSymbolAddress((void**)&p_yl, g_yl);
    cudaGetSymbolAddress((void**)&p_yr, g_yr);
    cudaGetSymbolAddress((void**)&p_h1, g_h1);
    cudaGetSymbolAddress((void**)&p_h2, g_h2h);
    cudaGetSymbolAddress((void**)&p_s1, g_s1);
    cudaGetSymbolAddress((void**)&p_t1, g_t1);
    cudaGetSymbolAddress((void**)&p_s2, g_s2);
    cudaGetSymbolAddress((void**)&p_t2, g_t2);

    dim3 gL((NN + 127) / 128, 2);

    // 1: pack Wc/bl, BN fold, segment bounds
    k_prep<<<512, 256>>>(Wih, Whh, bih, bhh, g1, be1, rm1, rv1, b1l,
                         g2, be2, rm2, rv2, b2l, batch);
    // 2-4: CSR build (self-cleaning counters; no zero kernel)
    k_hist<<<(EE + 255) / 256, 256>>>(ei);
    k_scan<<<1, 1024>>>();
    k_fill<<<(EE + 255) / 256, 256>>>(ei);

    // 5-6: layer 1
    k_gemm_tf32<<<gL, 256>>>(x, W1l, W1r, p_yl, p_yr);
    k_agg<<<(NN * 32 + 255) / 256, 256>>>(p_s1, p_t1, p_h1, nullptr, 0);
    // 7-8: layer 2 (h2 in fp16)
    k_gemm_tf32<<<gL, 256>>>(p_h1, W2l, W2r, p_yl, p_yr);
    k_agg<<<(NN * 32 + 255) / 256, 256>>>(p_s2, p_t2, nullptr, p_h2, 1);

    // 9: fused set2set (3 steps) + final projection -> d_out
    k_s2s<<<BB / 4, 256>>>(Wp, bp, (float*)d_out);
}

// round 8
// speedup vs baseline: 1.9224x; 1.2048x over previous
#include <cuda_runtime.h>
#include <cuda_fp16.h>
#include <cstdint>

#define NN 40000
#define EE 640000
#define BB 256

// ---------------- scratch (device globals; no allocation, zero-initialized) ----------------
__device__ __half g_yl[NN * 128];      // lin_l output (gathered) fp16
__device__ __half g_yr[NN * 128];      // lin_r output fp16
__device__ float g_h1[NN * 128];       // layer-1 output (GEMM input) fp32
__device__ __half g_h2h[NN * 128];     // layer-2 output (s2s attention input) fp16
__device__ float g_inv[NN];
__device__ int   g_dc[2 * NN];         // deg | cursor (self-cleaning: k_scan re-zeroes)
__device__ int   g_start[NN + 1];
__device__ int   g_csr[EE];            // src ids sorted by dst
__device__ int   g_seg[BB + 1];
__device__ float g_Wc[512 * 256];      // [Wih[:,:128]+Whh | Wih[:,128:]]
__device__ float g_bl[512];            // bih + bhh
__device__ float g_s1[128], g_t1[128], g_s2[128], g_t2[128];

// ---------------- helpers ----------------
__device__ __forceinline__ float sigmoidf_(float x) { return 1.f / (1.f + expf(-x)); }

__device__ __forceinline__ float to_tf32(float x) {
    uint32_t u;
    asm("cvt.rna.tf32.f32 %0, %1;" : "=r"(u) : "f"(x));
    return __uint_as_float(u);
}

__device__ __forceinline__ void mma_tf32(float c[4], uint32_t a0, uint32_t a1,
                                         uint32_t a2, uint32_t a3,
                                         uint32_t b0, uint32_t b1) {
    asm volatile(
        "mma.sync.aligned.m16n8k8.row.col.f32.tf32.tf32.f32 "
        "{%0,%1,%2,%3}, {%4,%5,%6,%7}, {%8,%9}, {%0,%1,%2,%3};\n"
        : "+f"(c[0]), "+f"(c[1]), "+f"(c[2]), "+f"(c[3])
        : "r"(a0), "r"(a1), "r"(a2), "r"(a3), "r"(b0), "r"(b1));
}

__device__ __forceinline__ float dot8(float4 w0, float4 w1, float4 v0, float4 v1) {
    return w0.x * v0.x + w0.y * v0.y + w0.z * v0.z + w0.w * v0.w
         + w1.x * v1.x + w1.y * v1.y + w1.z * v1.z + w1.w * v1.w;
}

// ---------------- pack Wc/bl, fold BN, segment bounds ----------------
__global__ void k_prep(const float* __restrict__ Wih, const float* __restrict__ Whh,
                       const float* __restrict__ bih, const float* __restrict__ bhh,
                       const float* __restrict__ g1, const float* __restrict__ be1,
                       const float* __restrict__ rm1, const float* __restrict__ rv1,
                       const float* __restrict__ b1l,
                       const float* __restrict__ g2, const float* __restrict__ be2,
                       const float* __restrict__ rm2, const float* __restrict__ rv2,
                       const float* __restrict__ b2l,
                       const int* __restrict__ batch) {
    int i = blockIdx.x * blockDim.x + threadIdx.x;
    if (i < 512 * 256) {
        int r = i >> 8, k = i & 255;
        float w = Wih[r * 256 + k];
        if (k < 128) w += Whh[r * 128 + k];
        g_Wc[i] = w;
    }
    if (i < 512) g_bl[i] = bih[i] + bhh[i];
    if (i < 128) {
        float s = g1[i] * rsqrtf(rv1[i] + 1e-5f);
        g_s1[i] = s; g_t1[i] = be1[i] + (b1l[i] - rm1[i]) * s;
    } else if (i < 256) {
        int j = i - 128;
        float s = g2[j] * rsqrtf(rv2[j] + 1e-5f);
        g_s2[j] = s; g_t2[j] = be2[j] + (b2l[j] - rm2[j]) * s;
    }
    if (i < NN) {
        int b = batch[i];
        int prev = (i == 0) ? -1 : batch[i - 1];
        for (int q = prev + 1; q <= b; q++) g_seg[q] = i;
        if (i == NN - 1)
            for (int q = b + 1; q <= BB; q++) g_seg[q] = NN;
    }
}

// ---------------- CSR build (self-cleaning counters) ----------------
__global__ void k_hist(const int* __restrict__ ei) {
    int e = blockIdx.x * blockDim.x + threadIdx.x;
    if (e < EE) atomicAdd(&g_dc[ei[EE + e]], 1);
}

__global__ void k_scan() {  // single block, 1024 threads
    __shared__ int part[1024];
    int tid = threadIdx.x;
    const int chunk = (NN + 1023) / 1024;
    int b0 = tid * chunk, b1 = min(b0 + chunk, NN);
    int s = 0;
    for (int i = b0; i < b1; i++) s += g_dc[i];
    part[tid] = s;
    __syncthreads();
    for (int off = 1; off < 1024; off <<= 1) {
        int v = (tid >= off) ? part[tid - off] : 0;
        __syncthreads();
        part[tid] += v;
        __syncthreads();
    }
    int base = (tid == 0) ? 0 : part[tid - 1];
    for (int i = b0; i < b1; i++) {
        int d = g_dc[i];
        g_start[i] = base;
        g_inv[i] = 1.f / (float)max(d, 1);
        base += d;
        g_dc[i] = 0;          // re-zero degree half for next call
        g_dc[NN + i] = 0;     // zero cursor half for k_fill below
    }
    if (tid == 1023) g_start[NN] = base;
}

__global__ void k_fill(const int* __restrict__ ei) {
    int e = blockIdx.x * blockDim.x + threadIdx.x;
    if (e >= EE) return;
    int s = ei[e], d = ei[EE + e];
    int pos = g_start[d] + atomicAdd(&g_dc[NN + d], 1);
    g_csr[pos] = s;
}

// ---------------- tf32 tensor-core GEMM: Yl/Yr = A @ Wl^T / Wr^T (fp16 out) ----------------
__global__ __launch_bounds__(256) void k_gemm_tf32(
    const float* __restrict__ A,
    const float* __restrict__ Wl, const float* __restrict__ Wr,
    __half* __restrict__ Yl, __half* __restrict__ Yr) {
    __shared__ float As[32][133];   // [k][m]
    __shared__ float Bs[32][133];   // [k][n]
    const float* W = blockIdx.y ? Wr : Wl;
    __half* Y = blockIdx.y ? Yr : Yl;
    int m0 = blockIdx.x * 128;
    int tid = threadIdx.x;
    int warp = tid >> 5, lane = tid & 31;
    int wm = warp >> 1, wn = warp & 1;
    int gid = lane >> 2, tig = lane & 3;

    float acc[2][8][4];
#pragma unroll
    for (int i = 0; i < 2; i++)
#pragma unroll
        for (int j = 0; j < 8; j++)
#pragma unroll
            for (int q = 0; q < 4; q++) acc[i][j][q] = 0.f;

    int lrow = tid >> 3;
    int lk4 = (tid & 7) * 4;

    for (int kc = 0; kc < 128; kc += 32) {
#pragma unroll
        for (int i = 0; i < 4; i++) {
            int r = m0 + lrow + 32 * i;
            int rc = min(r, NN - 1);
            float4 v = *(const float4*)(A + (size_t)rc * 128 + kc + lk4);
            As[lk4 + 0][lrow + 32 * i] = to_tf32(v.x);
            As[lk4 + 1][lrow + 32 * i] = to_tf32(v.y);
            As[lk4 + 2][lrow + 32 * i] = to_tf32(v.z);
            As[lk4 + 3][lrow + 32 * i] = to_tf32(v.w);
            float4 w = *(const float4*)(W + (size_t)(lrow + 32 * i) * 128 + kc + lk4);
            Bs[lk4 + 0][lrow + 32 * i] = to_tf32(w.x);
            Bs[lk4 + 1][lrow + 32 * i] = to_tf32(w.y);
            Bs[lk4 + 2][lrow + 32 * i] = to_tf32(w.z);
            Bs[lk4 + 3][lrow + 32 * i] = to_tf32(w.w);
        }
        __syncthreads();
#pragma unroll
        for (int ks = 0; ks < 32; ks += 8) {
            uint32_t a[2][4];
#pragma unroll
            for (int mt = 0; mt < 2; mt++) {
                int mb = wm * 32 + mt * 16;
                a[mt][0] = __float_as_uint(As[ks + tig][mb + gid]);
                a[mt][1] = __float_as_uint(As[ks + tig][mb + gid + 8]);
                a[mt][2] = __float_as_uint(As[ks + tig + 4][mb + gid]);
                a[mt][3] = __float_as_uint(As[ks + tig + 4][mb + gid + 8]);
            }
#pragma unroll
            for (int nt = 0; nt < 8; nt++) {
                int nb = wn * 64 + nt * 8;
                uint32_t b0 = __float_as_uint(Bs[ks + tig][nb + gid]);
                uint32_t b1 = __float_as_uint(Bs[ks + tig + 4][nb + gid]);
                mma_tf32(acc[0][nt], a[0][0], a[0][1], a[0][2], a[0][3], b0, b1);
                mma_tf32(acc[1][nt], a[1][0], a[1][1], a[1][2], a[1][3], b0, b1);
            }
        }
        __syncthreads();
    }

    int ncol0 = wn * 64;
#pragma unroll
    for (int mt = 0; mt < 2; mt++) {
        int row0 = m0 + wm * 32 + mt * 16 + gid;
        int row1 = row0 + 8;
#pragma unroll
        for (int nt = 0; nt < 8; nt++) {
            int c = ncol0 + nt * 8 + tig * 2;
            if (row0 < NN)
                *(__half2*)(Y + (size_t)row0 * 128 + c) =
                    __floats2half2_rn(acc[mt][nt][0], acc[mt][nt][1]);
            if (row1 < NN)
                *(__half2*)(Y + (size_t)row1 * 128 + c) =
                    __floats2half2_rn(acc[mt][nt][2], acc[mt][nt][3]);
        }
    }
}

// ---------------- CSR aggregation + epilogue (fp16 gather, fp32 accum) ----------------
__global__ void k_agg(const float* __restrict__ s, const float* __restrict__ t,
                      float* __restrict__ out32, __half* __restrict__ out16,
                      int fp16out) {
    int gt = blockIdx.x * blockDim.x + threadIdx.x;
    int w = gt >> 5;
    if (w >= NN) return;
    int lane = gt & 31;
    int e0 = g_start[w], e1 = g_start[w + 1];
    float4 acc0 = make_float4(0.f, 0.f, 0.f, 0.f);
    float4 acc1 = make_float4(0.f, 0.f, 0.f, 0.f);
    const uint2* Yl2 = (const uint2*)g_yl;
    int e = e0;
    for (; e + 2 <= e1; e += 2) {
        int sa = __ldg(g_csr + e);
        int sb = __ldg(g_csr + e + 1);
        uint2 ua = Yl2[(size_t)sa * 32 + lane];
        uint2 ub = Yl2[(size_t)sb * 32 + lane];
        float2 a0 = __half22float2(*(__half2*)&ua.x);
        float2 a1 = __half22float2(*(__half2*)&ua.y);
        float2 b0 = __half22float2(*(__half2*)&ub.x);
        float2 b1 = __half22float2(*(__half2*)&ub.y);
        acc0.x += a0.x; acc0.y += a0.y; acc0.z += a1.x; acc0.w += a1.y;
        acc1.x += b0.x; acc1.y += b0.y; acc1.z += b1.x; acc1.w += b1.y;
    }
    if (e < e1) {
        int sa = __ldg(g_csr + e);
        uint2 ua = Yl2[(size_t)sa * 32 + lane];
        float2 a0 = __half22float2(*(__half2*)&ua.x);
        float2 a1 = __half22float2(*(__half2*)&ua.y);
        acc0.x += a0.x; acc0.y += a0.y; acc0.z += a1.x; acc0.w += a1.y;
    }
    acc0.x += acc1.x; acc0.y += acc1.y; acc0.z += acc1.z; acc0.w += acc1.w;
    float iv = g_inv[w];
    uint2 ur = ((const uint2*)g_yr)[(size_t)w * 32 + lane];
    float2 r0 = __half22float2(*(__half2*)&ur.x);
    float2 r1 = __half22float2(*(__half2*)&ur.y);
    float4 sv = ((const float4*)s)[lane];
    float4 tv = ((const float4*)t)[lane];
    float4 o;
    o.x = fmaxf(fmaf(fmaf(acc0.x, iv, r0.x), sv.x, tv.x), 0.f);
    o.y = fmaxf(fmaf(fmaf(acc0.y, iv, r0.y), sv.y, tv.y), 0.f);
    o.z = fmaxf(fmaf(fmaf(acc0.z, iv, r1.x), sv.z, tv.z), 0.f);
    o.w = fmaxf(fmaf(fmaf(acc0.w, iv, r1.y), sv.w, tv.w), 0.f);
    if (fp16out) {
        uint2 pk;
        *(__half2*)&pk.x = __floats2half2_rn(o.x, o.y);
        *(__half2*)&pk.y = __floats2half2_rn(o.z, o.w);
        ((uint2*)out16)[(size_t)w * 32 + lane] = pk;
    } else {
        ((float4*)out32)[(size_t)w * 32 + lane] = o;
    }
}

// ---------------- fused set2set (3 steps) + final projection ----------------
// 128 blocks x 256 threads; 2 graphs per block, 4 warps per graph (latency-optimized).
// Pass 1 caches attention logits in shared so pass 2 has NO shfl chains.
#define ESLOTS 384
__global__ __launch_bounds__(256) void k_s2s(const float* __restrict__ Wp,
                                             const float* __restrict__ bp,
                                             float* __restrict__ out) {
    int blk = blockIdx.x;
    int tid = threadIdx.x;
    int warp = tid >> 5, lane = tid & 31;
    int gr = warp >> 2;              // graph slot 0/1
    int wl = warp & 3;               // warp-local index within graph
    int g = blk * 2 + gr;

    __shared__ float sh_v[2][256];       // q_star = [q | r]
    __shared__ float sh_q[2][128];
    __shared__ float sh_c[2][128];
    __shared__ float sh_gates[2][512];
    __shared__ float sh_r[2][4][128];
    __shared__ float sh_s[2][8];         // [graph][0..3 = max, 4..7 = sum]
    __shared__ float sh_e[2][ESLOTS];    // cached logits

    if (tid < 128) { sh_c[0][tid] = 0.f; sh_c[1][tid] = 0.f; }
    __syncthreads();

    int s0 = g_seg[g], s1 = g_seg[g + 1];
    int cnt = s1 - s0;
    const uint2* H2 = (const uint2*)g_h2h;   // 4 halves per uint2; row = 32 uint2

    for (int step = 0; step < 3; step++) {
        // ---- gates ----
        if (step == 0) {
            float b0 = g_bl[tid], b1 = g_bl[256 + tid];
            sh_gates[0][tid] = b0; sh_gates[0][256 + tid] = b1;
            sh_gates[1][tid] = b0; sh_gates[1][256 + tid] = b1;
        } else {
            const float4* VA = (const float4*)sh_v[0];
            const float4* VB = (const float4*)sh_v[1];
            float4 va0 = VA[lane], va1 = VA[32 + lane];
            float4 vb0 = VB[lane], vb1 = VB[32 + lane];
#pragma unroll 4
            for (int j = 0; j < 64; j++) {
                int r = warp * 64 + j;
                const float4* Wr4 = (const float4*)(g_Wc + (size_t)r * 256);
                float4 w0 = Wr4[lane], w1 = Wr4[32 + lane];
                float pA = dot8(w0, w1, va0, va1);
                float pB = dot8(w0, w1, vb0, vb1);
#pragma unroll
                for (int o = 16; o > 0; o >>= 1) {
                    pA += __shfl_xor_sync(0xffffffffu, pA, o);
                    pB += __shfl_xor_sync(0xffffffffu, pB, o);
                }
                if (lane == 0) {
                    float bb = g_bl[r];
                    sh_gates[0][r] = pA + bb;
                    sh_gates[1][r] = pB + bb;
                }
            }
        }
        __syncthreads();

        // ---- LSTM cell (2 graphs x 128 dims over 256 threads) ----
        {
            int gg = tid >> 7, d = tid & 127;
            float ig = sh_gates[gg][d], fg = sh_gates[gg][128 + d];
            float gv = sh_gates[gg][256 + d], og = sh_gates[gg][384 + d];
            float c0 = sh_c[gg][d];
            float cn = sigmoidf_(fg) * c0 + sigmoidf_(ig) * tanhf(gv);
            float hn = sigmoidf_(og) * tanhf(cn);
            sh_c[gg][d] = cn;
            sh_q[gg][d] = hn;
        }
        __syncthreads();

        // ---- attention pass 1: dots + segment max; cache logits ----
        float4 qv = ((const float4*)sh_q[gr])[lane];
        float wmax = -3.402823466e38f;
        for (int idx = wl; idx < cnt; idx += 4) {
            uint2 u = H2[(size_t)(s0 + idx) * 32 + lane];
            float2 h0 = __half22float2(*(__half2*)&u.x);
            float2 h1 = __half22float2(*(__half2*)&u.y);
            float p = h0.x * qv.x + h0.y * qv.y + h1.x * qv.z + h1.y * qv.w;
#pragma unroll
            for (int o = 16; o > 0; o >>= 1) p += __shfl_xor_sync(0xffffffffu, p, o);
            if (lane == 0 && idx < ESLOTS) sh_e[gr][idx] = p;
            wmax = fmaxf(wmax, p);
        }
        if (lane == 0) sh_s[gr][wl] = wmax;
        __syncthreads();
        float emax = fmaxf(fmaxf(sh_s[gr][0], sh_s[gr][1]),
                           fmaxf(sh_s[gr][2], sh_s[gr][3]));

        // ---- attention pass 2: pure streaming (no shfl) ----
        float asum = 0.f;
        float4 racc = make_float4(0.f, 0.f, 0.f, 0.f);
        for (int idx = wl; idx < cnt; idx += 4) {
            float e;
            if (idx < ESLOTS) {
                e = sh_e[gr][idx];
            } else {  // cold fallback (segment larger than cache; effectively never)
                uint2 u0 = H2[(size_t)(s0 + idx) * 32 + lane];
                float2 c0 = __half22float2(*(__half2*)&u0.x);
                float2 c1 = __half22float2(*(__half2*)&u0.y);
                float p = c0.x * qv.x + c0.y * qv.y + c1.x * qv.z + c1.y * qv.w;
#pragma unroll
                for (int o = 16; o > 0; o >>= 1) p += __shfl_xor_sync(0xffffffffu, p, o);
                e = p;
            }
            float a = expf(e - emax);
            uint2 u = H2[(size_t)(s0 + idx) * 32 + lane];
            float2 h0 = __half22float2(*(__half2*)&u.x);
            float2 h1 = __half22float2(*(__half2*)&u.y);
            asum += a;
            racc.x += a * h0.x; racc.y += a * h0.y; racc.z += a * h1.x; racc.w += a * h1.y;
        }
        ((float4*)sh_r[gr][wl])[lane] = racc;
        if (lane == 0) sh_s[gr][4 + wl] = asum;
        __syncthreads();

        // ---- combine: q_star = [q | r] ----
        {
            int gg = tid >> 7, d = tid & 127;
            float den = sh_s[gg][4] + sh_s[gg][5] + sh_s[gg][6] + sh_s[gg][7];
            float rsum = sh_r[gg][0][d] + sh_r[gg][1][d] + sh_r[gg][2][d] + sh_r[gg][3][d];
            float r = (den > 0.f) ? rsum / den : 0.f;
            sh_v[gg][d] = sh_q[gg][d];
            sh_v[gg][128 + d] = r;
        }
        __syncthreads();
    }

    // ---- final projection: each Wp row serves both graphs ----
    {
        const float4* VA = (const float4*)sh_v[0];
        const float4* VB = (const float4*)sh_v[1];
        float4 va0 = VA[lane], va1 = VA[32 + lane];
        float4 vb0 = VB[lane], vb1 = VB[32 + lane];
#pragma unroll 4
        for (int j = 0; j < 16; j++) {
            int row = warp * 16 + j;
            const float4* Wr4 = (const float4*)(Wp + (size_t)row * 256);
            float4 w0 = Wr4[lane], w1 = Wr4[32 + lane];
            float pA = dot8(w0, w1, va0, va1);
            float pB = dot8(w0, w1, vb0, vb1);
#pragma unroll
            for (int o = 16; o > 0; o >>= 1) {
                pA += __shfl_xor_sync(0xffffffffu, pA, o);
                pB += __shfl_xor_sync(0xffffffffu, pB, o);
            }
            if (lane == 0) {
                float bb = bp[row];
                out[(blk * 2 + 0) * 128 + row] = pA + bb;
                out[(blk * 2 + 1) * 128 + row] = pB + bb;
            }
        }
    }
}

// ---------------- host ----------------
extern "C" void kernel_launch(void* const* d_in, const int* in_sizes, int n_in,
                              void* d_out, int out_size) {
    const float* x    = (const float*)d_in[0];
    const int*   ei   = (const int*)d_in[1];
    const int*   batch= (const int*)d_in[2];
    const float* W1l  = (const float*)d_in[3];
    const float* b1l  = (const float*)d_in[4];
    const float* W1r  = (const float*)d_in[5];
    const float* g1   = (const float*)d_in[6];
    const float* be1  = (const float*)d_in[7];
    const float* rm1  = (const float*)d_in[8];
    const float* rv1  = (const float*)d_in[9];
    const float* W2l  = (const float*)d_in[10];
    const float* b2l  = (const float*)d_in[11];
    const float* W2r  = (const float*)d_in[12];
    const float* g2   = (const float*)d_in[13];
    const float* be2  = (const float*)d_in[14];
    const float* rm2  = (const float*)d_in[15];
    const float* rv2  = (const float*)d_in[16];
    const float* Wih  = (const float*)d_in[17];
    const float* Whh  = (const float*)d_in[18];
    const float* bih  = (const float*)d_in[19];
    const float* bhh  = (const float*)d_in[20];
    const float* Wp   = (const float*)d_in[21];
    const float* bp   = (const float*)d_in[22];

    __half *p_yl, *p_yr, *p_h2;
    float *p_h1, *p_s1, *p_t1, *p_s2, *p_t2;
    cudaGetSymbolAddress((void**)&p_yl, g_yl);
    cudaGetSymbolAddress((void**)&p_yr, g_yr);
    cudaGetSymbolAddress((void**)&p_h1, g_h1);
    cudaGetSymbolAddress((void**)&p_h2, g_h2h);
    cudaGetSymbolAddress((void**)&p_s1, g_s1);
    cudaGetSymbolAddress((void**)&p_t1, g_t1);
    cudaGetSymbolAddress((void**)&p_s2, g_s2);
    cudaGetSymbolAddress((void**)&p_t2, g_t2);

    dim3 gL((NN + 127) / 128, 2);

    // 1: pack Wc/bl, BN fold, segment bounds
    k_prep<<<512, 256>>>(Wih, Whh, bih, bhh, g1, be1, rm1, rv1, b1l,
                         g2, be2, rm2, rv2, b2l, batch);
    // 2-4: CSR build (self-cleaning counters; no zero kernel)
    k_hist<<<(EE + 255) / 256, 256>>>(ei);
    k_scan<<<1, 1024>>>();
    k_fill<<<(EE + 255) / 256, 256>>>(ei);

    // 5-6: layer 1
    k_gemm_tf32<<<gL, 256>>>(x, W1l, W1r, p_yl, p_yr);
    k_agg<<<(NN * 32 + 255) / 256, 256>>>(p_s1, p_t1, p_h1, nullptr, 0);
    // 7-8: layer 2 (h2 in fp16)
    k_gemm_tf32<<<gL, 256>>>(p_h1, W2l, W2r, p_yl, p_yr);
    k_agg<<<(NN * 32 + 255) / 256, 256>>>(p_s2, p_t2, nullptr, p_h2, 1);

    // 9: fused set2set (3 steps) + final projection -> d_out
    k_s2s<<<BB / 2, 256>>>(Wp, bp, (float*)d_out);
}